// round 10
// baseline (speedup 1.0000x reference)
#include <cuda_runtime.h>
#include <math.h>

#define MAX_BLOCKS 65536
__device__ float        g_partials[MAX_BLOCKS];
__device__ unsigned int g_done;        // zero at load; last block resets each launch

static constexpr int D = 512;          // feature dim (float32)
static constexpr int BLOCK = 256;      // 8 warps per block, 1 warp per edge

__device__ __forceinline__ void stcg(float* p, float v) {
    asm volatile("st.global.cg.f32 [%0], %1;" :: "l"(p), "f"(v) : "memory");
}
__device__ __forceinline__ float4 ldcg4(const float4* p) {
    float4 v;
    asm volatile("ld.global.cg.v4.f32 {%0,%1,%2,%3}, [%4];"
                 : "=f"(v.x), "=f"(v.y), "=f"(v.z), "=f"(v.w) : "l"(p));
    return v;
}
// Release atomic: orders the prior .cg partial store before the counter bump
// WITHOUT a fence instruction (no CCTL.IVALL -> L1 reuse preserved).
__device__ __forceinline__ unsigned int atom_add_release(unsigned int* p, unsigned int v) {
    unsigned int old;
    asm volatile("atom.global.add.release.gpu.u32 %0, [%1], %2;"
                 : "=r"(old) : "l"(p), "r"(v) : "memory");
    return old;
}

// One warp per edge (proven mainloop — unchanged). Tail: warps 1-7 exit after
// the block reduce; warp 0 posts the partial + release-increments the done
// counter; the LAST block's warp 0 reduces all partials and writes the mean.
__global__ void __launch_bounds__(BLOCK) edge_loss_kernel(
    const float* __restrict__ feat,
    const int*   __restrict__ pos_src,
    const int*   __restrict__ pos_dst,
    const int*   __restrict__ neg_src,
    const int*   __restrict__ neg_dst,
    int e_pos, int e_total, int n_blocks, float inv_total,
    float* __restrict__ out)
{
    const int warp_global = (blockIdx.x * BLOCK + threadIdx.x) >> 5;
    const int lane = threadIdx.x & 31;
    const int wid  = threadIdx.x >> 5;

    float term = 0.0f;

    if (warp_global < e_total) {
        int s, d;
        const bool is_pos = (warp_global < e_pos);
        if (is_pos) {
            s = pos_src[warp_global];
            d = pos_dst[warp_global];
        } else {
            s = neg_src[warp_global - e_pos];
            d = neg_dst[warp_global - e_pos];
        }

        const float4* __restrict__ u =
            reinterpret_cast<const float4*>(feat + (size_t)s * D);
        const float4* __restrict__ v =
            reinterpret_cast<const float4*>(feat + (size_t)d * D);

        // 512 floats = 128 float4 per row; each lane takes 4 at stride 32.
        // All 8 vector loads issued up front for maximum MLP.
        float4 a0 = u[lane +  0];
        float4 a1 = u[lane + 32];
        float4 a2 = u[lane + 64];
        float4 a3 = u[lane + 96];
        float4 b0 = v[lane +  0];
        float4 b1 = v[lane + 32];
        float4 b2 = v[lane + 64];
        float4 b3 = v[lane + 96];

        float acc = 0.0f;
        acc = fmaf(a0.x, b0.x, acc); acc = fmaf(a0.y, b0.y, acc);
        acc = fmaf(a0.z, b0.z, acc); acc = fmaf(a0.w, b0.w, acc);
        acc = fmaf(a1.x, b1.x, acc); acc = fmaf(a1.y, b1.y, acc);
        acc = fmaf(a1.z, b1.z, acc); acc = fmaf(a1.w, b1.w, acc);
        acc = fmaf(a2.x, b2.x, acc); acc = fmaf(a2.y, b2.y, acc);
        acc = fmaf(a2.z, b2.z, acc); acc = fmaf(a2.w, b2.w, acc);
        acc = fmaf(a3.x, b3.x, acc); acc = fmaf(a3.y, b3.y, acc);
        acc = fmaf(a3.z, b3.z, acc); acc = fmaf(a3.w, b3.w, acc);

        // Warp reduce (deterministic tree).
        #pragma unroll
        for (int off = 16; off > 0; off >>= 1)
            acc += __shfl_xor_sync(0xffffffffu, acc, off);

        const float lab = is_pos ? 1.0f : 0.0f;
        term = fmaxf(acc, 0.0f) - acc * lab + log1pf(expf(-fabsf(acc)));
    }

    __shared__ float smem[BLOCK / 32];
    if (lane == 0) smem[wid] = term;
    __syncthreads();
    if (wid != 0) return;                 // warps 1-7 retire immediately

    // --- warp 0 only from here ---
    int last = 0;
    if (lane == 0) {
        float bsum = 0.0f;
        #pragma unroll
        for (int i = 0; i < BLOCK / 32; i++) bsum += smem[i];
        stcg(&g_partials[blockIdx.x], bsum);
        unsigned int old = atom_add_release(&g_done, 1u);
        last = (old == (unsigned int)(n_blocks - 1));
    }
    last = __shfl_sync(0xffffffffu, last, 0);
    if (!last) return;

    // Last block's warp 0: reduce all partials (fixed order -> deterministic).
    // 25000 floats = 6250 float4; ~196/lane in 4 independent chains.
    const float4* p4 = reinterpret_cast<const float4*>(g_partials);
    const int n4 = n_blocks >> 2;
    float a0 = 0.0f, a1 = 0.0f, a2 = 0.0f, a3 = 0.0f;
    int i = lane;
    for (; i + 96 < n4; i += 128) {
        float4 v0 = ldcg4(&p4[i +  0]);
        float4 v1 = ldcg4(&p4[i + 32]);
        float4 v2 = ldcg4(&p4[i + 64]);
        float4 v3 = ldcg4(&p4[i + 96]);
        a0 += (v0.x + v0.y) + (v0.z + v0.w);
        a1 += (v1.x + v1.y) + (v1.z + v1.w);
        a2 += (v2.x + v2.y) + (v2.z + v2.w);
        a3 += (v3.x + v3.y) + (v3.z + v3.w);
    }
    for (; i < n4; i += 32) {
        float4 v = ldcg4(&p4[i]);
        a0 += (v.x + v.y) + (v.z + v.w);
    }
    if (lane < (n_blocks & 3))
        a1 += g_partials[(n4 << 2) + lane];

    float t = (a0 + a1) + (a2 + a3);
    #pragma unroll
    for (int off = 16; off > 0; off >>= 1)
        t += __shfl_xor_sync(0xffffffffu, t, off);

    if (lane == 0) {
        *out   = t * inv_total;
        g_done = 0;                       // reset for next graph replay
    }
}

extern "C" void kernel_launch(void* const* d_in, const int* in_sizes, int n_in,
                              void* d_out, int out_size)
{
    const float* feat    = (const float*)d_in[0];
    const int*   pos_src = (const int*)d_in[1];
    const int*   pos_dst = (const int*)d_in[2];
    const int*   neg_src = (const int*)d_in[3];
    const int*   neg_dst = (const int*)d_in[4];
    float* out = (float*)d_out;

    const int e_pos   = in_sizes[1];
    const int e_neg   = in_sizes[3];
    const int e_total = e_pos + e_neg;

    const int warps_per_block = BLOCK / 32;
    int n_blocks = (e_total + warps_per_block - 1) / warps_per_block;
    if (n_blocks > MAX_BLOCKS) n_blocks = MAX_BLOCKS;  // 200k edges -> 25000

    edge_loss_kernel<<<n_blocks, BLOCK>>>(feat, pos_src, pos_dst,
                                          neg_src, neg_dst,
                                          e_pos, e_total, n_blocks,
                                          1.0f / (float)e_total, out);
}

// round 11
// speedup vs baseline: 1.7830x; 1.7830x over previous
#include <cuda_runtime.h>
#include <math.h>

// Scratch for per-block partial sums (no device allocation allowed).
#define MAX_BLOCKS 65536
__device__ float g_partials[MAX_BLOCKS];

static constexpr int D = 512;          // feature dim (float32)
static constexpr int BLOCK = 256;      // 8 warps per block, 1 warp per edge

__device__ __forceinline__ float4 ldcg4(const float4* p) {
    float4 v;
    asm volatile("ld.global.cg.v4.f32 {%0,%1,%2,%3}, [%4];"
                 : "=f"(v.x), "=f"(v.y), "=f"(v.z), "=f"(v.w) : "l"(p));
    return v;
}

// Kernel 1: one warp per edge (proven mainloop), now with minBlocksPerSM=8
// to force <=32 regs/thread -> 64 resident warps/SM (100% occupancy) for
// better L2-latency hiding. No fences, no atomics anywhere.
__global__ void __launch_bounds__(BLOCK, 8) edge_loss_kernel(
    const float* __restrict__ feat,
    const int*   __restrict__ pos_src,
    const int*   __restrict__ pos_dst,
    const int*   __restrict__ neg_src,
    const int*   __restrict__ neg_dst,
    int e_pos, int e_total)
{
    const int warp_global = (blockIdx.x * BLOCK + threadIdx.x) >> 5;
    const int lane = threadIdx.x & 31;
    const int wid  = threadIdx.x >> 5;

    float term = 0.0f;

    if (warp_global < e_total) {
        int s, d;
        const bool is_pos = (warp_global < e_pos);
        if (is_pos) {
            s = pos_src[warp_global];
            d = pos_dst[warp_global];
        } else {
            s = neg_src[warp_global - e_pos];
            d = neg_dst[warp_global - e_pos];
        }

        const float4* __restrict__ u =
            reinterpret_cast<const float4*>(feat + (size_t)s * D);
        const float4* __restrict__ v =
            reinterpret_cast<const float4*>(feat + (size_t)d * D);

        // 512 floats = 128 float4 per row; each lane takes 4 at stride 32.
        // All 8 vector loads issued up front for maximum MLP.
        float4 a0 = u[lane +  0];
        float4 a1 = u[lane + 32];
        float4 a2 = u[lane + 64];
        float4 a3 = u[lane + 96];
        float4 b0 = v[lane +  0];
        float4 b1 = v[lane + 32];
        float4 b2 = v[lane + 64];
        float4 b3 = v[lane + 96];

        float acc = 0.0f;
        acc = fmaf(a0.x, b0.x, acc); acc = fmaf(a0.y, b0.y, acc);
        acc = fmaf(a0.z, b0.z, acc); acc = fmaf(a0.w, b0.w, acc);
        acc = fmaf(a1.x, b1.x, acc); acc = fmaf(a1.y, b1.y, acc);
        acc = fmaf(a1.z, b1.z, acc); acc = fmaf(a1.w, b1.w, acc);
        acc = fmaf(a2.x, b2.x, acc); acc = fmaf(a2.y, b2.y, acc);
        acc = fmaf(a2.z, b2.z, acc); acc = fmaf(a2.w, b2.w, acc);
        acc = fmaf(a3.x, b3.x, acc); acc = fmaf(a3.y, b3.y, acc);
        acc = fmaf(a3.z, b3.z, acc); acc = fmaf(a3.w, b3.w, acc);

        // Warp reduce (deterministic tree).
        #pragma unroll
        for (int off = 16; off > 0; off >>= 1)
            acc += __shfl_xor_sync(0xffffffffu, acc, off);

        const float lab = is_pos ? 1.0f : 0.0f;
        term = fmaxf(acc, 0.0f) - acc * lab + log1pf(expf(-fabsf(acc)));
    }

    __shared__ float smem[BLOCK / 32];
    if (lane == 0) smem[wid] = term;
    __syncthreads();
    if (threadIdx.x == 0) {
        float sum = 0.0f;
        #pragma unroll
        for (int i = 0; i < BLOCK / 32; i++) sum += smem[i];
        g_partials[blockIdx.x] = sum;
    }
}

// Kernel 2: single-block vectorized reduce (cost is fixed launch/drain
// overhead; body already proven insensitive). Fixed order -> deterministic.
__global__ void __launch_bounds__(1024) final_reduce_kernel(
    int n_partials, float inv_total, float* __restrict__ out)
{
    __shared__ float sm[1024];
    const int n4 = n_partials >> 2;
    const float4* p4 = reinterpret_cast<const float4*>(g_partials);

    float a0 = 0.0f, a1 = 0.0f, a2 = 0.0f, a3 = 0.0f;
    int i = threadIdx.x;
    for (; i + 3 * 1024 < n4; i += 4 * 1024) {
        float4 v0 = ldcg4(&p4[i + 0 * 1024]);
        float4 v1 = ldcg4(&p4[i + 1 * 1024]);
        float4 v2 = ldcg4(&p4[i + 2 * 1024]);
        float4 v3 = ldcg4(&p4[i + 3 * 1024]);
        a0 += (v0.x + v0.y) + (v0.z + v0.w);
        a1 += (v1.x + v1.y) + (v1.z + v1.w);
        a2 += (v2.x + v2.y) + (v2.z + v2.w);
        a3 += (v3.x + v3.y) + (v3.z + v3.w);
    }
    for (; i < n4; i += 1024) {
        float4 v = ldcg4(&p4[i]);
        a0 += (v.x + v.y) + (v.z + v.w);
    }
    if (threadIdx.x < (n_partials & 3))
        a1 += g_partials[(n4 << 2) + threadIdx.x];

    sm[threadIdx.x] = (a0 + a1) + (a2 + a3);
    __syncthreads();
    #pragma unroll
    for (int s = 512; s > 0; s >>= 1) {
        if (threadIdx.x < s) sm[threadIdx.x] += sm[threadIdx.x + s];
        __syncthreads();
    }
    if (threadIdx.x == 0) *out = sm[0] * inv_total;
}

extern "C" void kernel_launch(void* const* d_in, const int* in_sizes, int n_in,
                              void* d_out, int out_size)
{
    const float* feat    = (const float*)d_in[0];
    const int*   pos_src = (const int*)d_in[1];
    const int*   pos_dst = (const int*)d_in[2];
    const int*   neg_src = (const int*)d_in[3];
    const int*   neg_dst = (const int*)d_in[4];
    float* out = (float*)d_out;

    const int e_pos   = in_sizes[1];
    const int e_neg   = in_sizes[3];
    const int e_total = e_pos + e_neg;

    const int warps_per_block = BLOCK / 32;
    int n_blocks = (e_total + warps_per_block - 1) / warps_per_block;
    if (n_blocks > MAX_BLOCKS) n_blocks = MAX_BLOCKS;  // 200k edges -> 25000

    edge_loss_kernel<<<n_blocks, BLOCK>>>(feat, pos_src, pos_dst,
                                          neg_src, neg_dst, e_pos, e_total);
    final_reduce_kernel<<<1, 1024>>>(n_blocks, 1.0f / (float)e_total, out);
}

// round 12
// speedup vs baseline: 1.7906x; 1.0043x over previous
#include <cuda_runtime.h>
#include <math.h>

// Scratch for per-block partial sums (no device allocation allowed).
#define MAX_BLOCKS 65536
__device__ float g_partials[MAX_BLOCKS];

static constexpr int D = 512;          // feature dim (float32)
static constexpr int BLOCK = 256;      // 8 warps per block, 1 warp per edge

__device__ __forceinline__ float4 ldcg4(const float4* p) {
    float4 v;
    asm volatile("ld.global.cg.v4.f32 {%0,%1,%2,%3}, [%4];"
                 : "=f"(v.x), "=f"(v.y), "=f"(v.z), "=f"(v.w) : "l"(p));
    return v;
}

// Kernel 1: one warp per edge (proven ~53.5us mainloop — unchanged).
// Each CTA triggers PDL completion right after storing its partial so the
// dependent reduce kernel releases as early as possible.
__global__ void __launch_bounds__(BLOCK, 8) edge_loss_kernel(
    const float* __restrict__ feat,
    const int*   __restrict__ pos_src,
    const int*   __restrict__ pos_dst,
    const int*   __restrict__ neg_src,
    const int*   __restrict__ neg_dst,
    int e_pos, int e_total)
{
    const int warp_global = (blockIdx.x * BLOCK + threadIdx.x) >> 5;
    const int lane = threadIdx.x & 31;
    const int wid  = threadIdx.x >> 5;

    float term = 0.0f;

    if (warp_global < e_total) {
        int s, d;
        const bool is_pos = (warp_global < e_pos);
        if (is_pos) {
            s = pos_src[warp_global];
            d = pos_dst[warp_global];
        } else {
            s = neg_src[warp_global - e_pos];
            d = neg_dst[warp_global - e_pos];
        }

        const float4* __restrict__ u =
            reinterpret_cast<const float4*>(feat + (size_t)s * D);
        const float4* __restrict__ v =
            reinterpret_cast<const float4*>(feat + (size_t)d * D);

        // 512 floats = 128 float4 per row; each lane takes 4 at stride 32.
        // All 8 vector loads issued up front for maximum MLP.
        float4 a0 = u[lane +  0];
        float4 a1 = u[lane + 32];
        float4 a2 = u[lane + 64];
        float4 a3 = u[lane + 96];
        float4 b0 = v[lane +  0];
        float4 b1 = v[lane + 32];
        float4 b2 = v[lane + 64];
        float4 b3 = v[lane + 96];

        float acc = 0.0f;
        acc = fmaf(a0.x, b0.x, acc); acc = fmaf(a0.y, b0.y, acc);
        acc = fmaf(a0.z, b0.z, acc); acc = fmaf(a0.w, b0.w, acc);
        acc = fmaf(a1.x, b1.x, acc); acc = fmaf(a1.y, b1.y, acc);
        acc = fmaf(a1.z, b1.z, acc); acc = fmaf(a1.w, b1.w, acc);
        acc = fmaf(a2.x, b2.x, acc); acc = fmaf(a2.y, b2.y, acc);
        acc = fmaf(a2.z, b2.z, acc); acc = fmaf(a2.w, b2.w, acc);
        acc = fmaf(a3.x, b3.x, acc); acc = fmaf(a3.y, b3.y, acc);
        acc = fmaf(a3.z, b3.z, acc); acc = fmaf(a3.w, b3.w, acc);

        // Warp reduce (deterministic tree).
        #pragma unroll
        for (int off = 16; off > 0; off >>= 1)
            acc += __shfl_xor_sync(0xffffffffu, acc, off);

        const float lab = is_pos ? 1.0f : 0.0f;
        term = fmaxf(acc, 0.0f) - acc * lab + log1pf(expf(-fabsf(acc)));
    }

    __shared__ float smem[BLOCK / 32];
    if (lane == 0) smem[wid] = term;
    __syncthreads();
    if (threadIdx.x == 0) {
        float sum = 0.0f;
        #pragma unroll
        for (int i = 0; i < BLOCK / 32; i++) sum += smem[i];
        g_partials[blockIdx.x] = sum;
        // Release the PDL dependency for this CTA (partial is written).
        cudaTriggerProgrammaticLaunchCompletion();
    }
}

// Kernel 2: single-block vectorized reduce, launched with PDL so its
// scheduling/prologue overlaps kernel 1's drain. gridDepSync guarantees
// all g_partials stores are visible. Fixed order -> deterministic.
__global__ void __launch_bounds__(1024) final_reduce_kernel(
    int n_partials, float inv_total, float* __restrict__ out)
{
    cudaGridDependencySynchronize();

    __shared__ float sm[1024];
    const int n4 = n_partials >> 2;
    const float4* p4 = reinterpret_cast<const float4*>(g_partials);

    float a0 = 0.0f, a1 = 0.0f, a2 = 0.0f, a3 = 0.0f;
    int i = threadIdx.x;
    for (; i + 3 * 1024 < n4; i += 4 * 1024) {
        float4 v0 = ldcg4(&p4[i + 0 * 1024]);
        float4 v1 = ldcg4(&p4[i + 1 * 1024]);
        float4 v2 = ldcg4(&p4[i + 2 * 1024]);
        float4 v3 = ldcg4(&p4[i + 3 * 1024]);
        a0 += (v0.x + v0.y) + (v0.z + v0.w);
        a1 += (v1.x + v1.y) + (v1.z + v1.w);
        a2 += (v2.x + v2.y) + (v2.z + v2.w);
        a3 += (v3.x + v3.y) + (v3.z + v3.w);
    }
    for (; i < n4; i += 1024) {
        float4 v = ldcg4(&p4[i]);
        a0 += (v.x + v.y) + (v.z + v.w);
    }
    if (threadIdx.x < (n_partials & 3))
        a1 += g_partials[(n4 << 2) + threadIdx.x];

    sm[threadIdx.x] = (a0 + a1) + (a2 + a3);
    __syncthreads();
    #pragma unroll
    for (int s = 512; s > 0; s >>= 1) {
        if (threadIdx.x < s) sm[threadIdx.x] += sm[threadIdx.x + s];
        __syncthreads();
    }
    if (threadIdx.x == 0) *out = sm[0] * inv_total;
}

extern "C" void kernel_launch(void* const* d_in, const int* in_sizes, int n_in,
                              void* d_out, int out_size)
{
    const float* feat    = (const float*)d_in[0];
    const int*   pos_src = (const int*)d_in[1];
    const int*   pos_dst = (const int*)d_in[2];
    const int*   neg_src = (const int*)d_in[3];
    const int*   neg_dst = (const int*)d_in[4];
    float* out = (float*)d_out;

    const int e_pos   = in_sizes[1];
    const int e_neg   = in_sizes[3];
    const int e_total = e_pos + e_neg;

    const int warps_per_block = BLOCK / 32;
    int n_blocks = (e_total + warps_per_block - 1) / warps_per_block;
    if (n_blocks > MAX_BLOCKS) n_blocks = MAX_BLOCKS;  // 200k edges -> 25000

    edge_loss_kernel<<<n_blocks, BLOCK>>>(feat, pos_src, pos_dst,
                                          neg_src, neg_dst, e_pos, e_total);

    // Launch the reduce with Programmatic Dependent Launch so it overlaps
    // kernel 1's tail; it self-synchronizes via cudaGridDependencySynchronize.
    cudaLaunchAttribute attrs[1];
    attrs[0].id = cudaLaunchAttributeProgrammaticStreamSerialization;
    attrs[0].val.programmaticStreamSerializationAllowed = 1;

    cudaLaunchConfig_t cfg = {};
    cfg.gridDim  = dim3(1, 1, 1);
    cfg.blockDim = dim3(1024, 1, 1);
    cfg.dynamicSmemBytes = 0;
    cfg.stream   = 0;
    cfg.attrs    = attrs;
    cfg.numAttrs = 1;

    float inv_total = 1.0f / (float)e_total;
    cudaLaunchKernelEx(&cfg, final_reduce_kernel, n_blocks, inv_total, out);
}